// round 3
// baseline (speedup 1.0000x reference)
#include <cuda_runtime.h>
#include <stdint.h>
#include <math.h>

#define HN 64
#define GN 256
#define NTHREADS 256

__device__ __forceinline__ uint32_t rotl32(uint32_t x, uint32_t r){ return (x<<r)|(x>>(32u-r)); }

// Threefry-2x32, 20 rounds, JAX key schedule.
__device__ __forceinline__ void tf2x32(uint32_t k0, uint32_t k1, uint32_t c0, uint32_t c1,
                                       uint32_t &o0, uint32_t &o1){
  uint32_t ks2 = k0 ^ k1 ^ 0x1BD11BDAu;
  uint32_t x0 = c0 + k0;
  uint32_t x1 = c1 + k1;
  x0+=x1; x1=rotl32(x1,13); x1^=x0;
  x0+=x1; x1=rotl32(x1,15); x1^=x0;
  x0+=x1; x1=rotl32(x1,26); x1^=x0;
  x0+=x1; x1=rotl32(x1, 6); x1^=x0;
  x0+=k1;  x1+=ks2+1u;
  x0+=x1; x1=rotl32(x1,17); x1^=x0;
  x0+=x1; x1=rotl32(x1,29); x1^=x0;
  x0+=x1; x1=rotl32(x1,16); x1^=x0;
  x0+=x1; x1=rotl32(x1,24); x1^=x0;
  x0+=ks2; x1+=k0+2u;
  x0+=x1; x1=rotl32(x1,13); x1^=x0;
  x0+=x1; x1=rotl32(x1,15); x1^=x0;
  x0+=x1; x1=rotl32(x1,26); x1^=x0;
  x0+=x1; x1=rotl32(x1, 6); x1^=x0;
  x0+=k0;  x1+=k1+3u;
  x0+=x1; x1=rotl32(x1,17); x1^=x0;
  x0+=x1; x1=rotl32(x1,29); x1^=x0;
  x0+=x1; x1=rotl32(x1,16); x1^=x0;
  x0+=x1; x1=rotl32(x1,24); x1^=x0;
  x0+=k1;  x1+=ks2+4u;
  x0+=x1; x1=rotl32(x1,13); x1^=x0;
  x0+=x1; x1=rotl32(x1,15); x1^=x0;
  x0+=x1; x1=rotl32(x1,26); x1^=x0;
  x0+=x1; x1=rotl32(x1, 6); x1^=x0;
  x0+=ks2; x1+=k0+5u;
  o0=x0; o1=x1;
}

// JAX partitionable uniform -> gumbel
__device__ __forceinline__ float bits2gumbel(uint32_t b){
  float u = __uint_as_float((b>>9)|0x3f800000u) - 1.0f;
  const float tiny = 1.17549435e-38f;
  u = fmaxf(tiny, u + tiny);
  return -__logf(-__logf(u));
}

__device__ __forceinline__ float sig_fast(float x){
  return __fdividef(1.0f, 1.0f + __expf(-x));
}
__device__ __forceinline__ float tanh_fast(float x){
  return 1.0f - __fdividef(2.0f, 1.0f + __expf(2.0f*x));
}

__global__ void __launch_bounds__(NTHREADS, 1)
controller_kernel(const float* __restrict__ ef, const float* __restrict__ eo,
                  const float* __restrict__ wih_g, const float* __restrict__ whh_g,
                  const float* __restrict__ wprev_g, const float* __restrict__ wcurr_g,
                  const float* __restrict__ wout_g, const float* __restrict__ wops_g,
                  const float* __restrict__ bops_g, const float* __restrict__ abias_g,
                  float* __restrict__ out, int out_size)
{
  __shared__ float s_wprevT[HN*HN];   // [k*64 + j]
  __shared__ float s_wcurrT[HN*HN];
  __shared__ float s_wops[5*HN];
  __shared__ float s_eops[5*HN];
  __shared__ float s_ef[HN];
  __shared__ float s_wout[HN];
  __shared__ float s_bops[8];
  __shared__ float s_abias[8];
  __shared__ __align__(16) float s_x[HN];
  __shared__ __align__(16) float s_h[HN];
  __shared__ float s_c[HN];
  __shared__ float s_g[GN];
  __shared__ float s_prevh[7*HN];
  __shared__ float s_prevfc[7*HN];
  __shared__ float s_gum[40*6];
  __shared__ float s_dot[8];
  __shared__ int   s_a;

  const int tid  = threadIdx.x;
  const int lane = tid & 31;
  const int warp = tid >> 5;

  // ---- cooperative loads ----
  for (int i=tid;i<HN;i+=NTHREADS){ s_ef[i]=ef[i]; s_wout[i]=wout_g[i]; }
  for (int i=tid;i<5*HN;i+=NTHREADS){ s_eops[i]=eo[i]; s_wops[i]=wops_g[i]; }
  if (tid<5){ s_bops[tid]=bops_g[tid]; s_abias[tid]=abias_g[tid]; }
  for (int i=tid;i<HN*HN;i+=NTHREADS){
    int j=i>>6, k=i&63;
    s_wprevT[k*HN+j]=wprev_g[i];
    s_wcurrT[k*HN+j]=wcurr_g[i];
  }
  float wih[HN], whh[HN];
  #pragma unroll
  for (int k=0;k<HN;k++){ wih[k]=wih_g[tid*HN+k]; whh[k]=whh_g[tid*HN+k]; }

  // ---- Gumbel table (input-independent; partitionable threefry) ----
  if (tid < 40){
    int r = tid % 20;
    int within = r & 3;
    int nd = 2 + (r>>2);
    int n  = (within<2) ? nd : 5;
    uint32_t k0,k1;
    tf2x32(0u, 42u, 0u, (uint32_t)(tid+1), k0, k1);   // fold_in(key(42), step)
    for (int i=0;i<n;i++){
      uint32_t o0,o1; tf2x32(k0,k1, 0u, (uint32_t)i, o0,o1);
      s_gum[tid*6+i] = bits2gumbel(o0 ^ o1);
    }
  }
  __syncthreads();

  if (tid<HN){ s_h[tid]=0.f; s_c[tid]=0.f; s_x[tid]=s_ef[tid]; }

  int step = 0;

  auto lstm = [&](){
    __syncthreads();                       // covers prior x/h writes
    const float4* x4 = (const float4*)s_x;
    const float4* h4 = (const float4*)s_h;
    float a0=0.f,a1=0.f,a2=0.f,a3=0.f;
    #pragma unroll
    for (int k=0;k<16;k++){
      float4 xv = x4[k];
      a0=fmaf(wih[4*k+0],xv.x,a0); a1=fmaf(wih[4*k+1],xv.y,a1);
      a2=fmaf(wih[4*k+2],xv.z,a2); a3=fmaf(wih[4*k+3],xv.w,a3);
    }
    #pragma unroll
    for (int k=0;k<16;k++){
      float4 hv = h4[k];
      a0=fmaf(whh[4*k+0],hv.x,a0); a1=fmaf(whh[4*k+1],hv.y,a1);
      a2=fmaf(whh[4*k+2],hv.z,a2); a3=fmaf(whh[4*k+3],hv.w,a3);
    }
    s_g[tid]=(a0+a1)+(a2+a3);
    __syncthreads();
    if (tid<HN){
      float ig=s_g[tid], fg=s_g[HN+tid], gg=s_g[2*HN+tid], og=s_g[3*HN+tid];
      float c = sig_fast(fg)*s_c[tid] + sig_fast(ig)*tanh_fast(gg);
      s_c[tid]=c;
      s_h[tid]=sig_fast(og)*tanh_fast(c);
    }
    __syncthreads();
  };

  // warp-0 parallel softmax/argmax/entropy over n<=6 categories.
  // lgt per lane precomputed by caller (lane<n), -1e30 otherwise.
  auto sample = [&](int n, float lgt){
    float gum = (lane<n) ? (lgt + s_gum[step*6+lane]) : -1e30f;
    int idx = lane;
    #pragma unroll
    for (int off=4;off;off>>=1){
      float g2=__shfl_xor_sync(0xffffffffu,gum,off);
      int   i2=__shfl_xor_sync(0xffffffffu,idx,off);
      if (g2>gum || (g2==gum && i2<idx)){ gum=g2; idx=i2; }
    }
    float mx = lgt;
    #pragma unroll
    for (int off=4;off;off>>=1) mx = fmaxf(mx, __shfl_xor_sync(0xffffffffu,mx,off));
    float e = (lane<n) ? __expf(lgt-mx) : 0.f;
    float se = e;
    #pragma unroll
    for (int off=4;off;off>>=1) se += __shfl_xor_sync(0xffffffffu,se,off);
    float lse = __logf(se);
    float lp = lgt - mx - lse;
    float ec = (lane<n) ? -__expf(lp)*lp : 0.f;
    #pragma unroll
    for (int off=4;off;off>>=1) ec += __shfl_xor_sync(0xffffffffu,ec,off);
    float lpa = __shfl_sync(0xffffffffu, lp, idx);
    if (lane==0){
      if (step    < out_size) out[step]    = (float)idx;
      if (40+step < out_size) out[40+step] = ec;
      if (80+step < out_size) out[80+step] = lpa;
      s_a = idx;
    }
  };

  for (int cell=0; cell<2; cell++){
    // two warm-up steps: prev_h <- 0, prev_fc <- h @ w_index_prev.T
    for (int t=0;t<2;t++){
      lstm();
      if (tid<HN){
        float b0=0.f,b1=0.f,b2=0.f,b3=0.f;
        #pragma unroll 16
        for (int k=0;k<HN;k+=4){
          b0=fmaf(s_h[k  ], s_wprevT[(k  )*HN+tid], b0);
          b1=fmaf(s_h[k+1], s_wprevT[(k+1)*HN+tid], b1);
          b2=fmaf(s_h[k+2], s_wprevT[(k+2)*HN+tid], b2);
          b3=fmaf(s_h[k+3], s_wprevT[(k+3)*HN+tid], b3);
        }
        s_prevfc[t*HN+tid]=(b0+b1)+(b2+b3);
        s_prevh[t*HN+tid]=0.f;
      }
      __syncthreads();
    }
    for (int node=2; node<7; node++){
      // ---- 2 index draws ----
      for (int t=0;t<2;t++){
        lstm();
        if (warp < node){
          // fused: lg for this warp's two lanes, then q-dot
          float lg0=0.f, lg1=0.f;
          #pragma unroll 16
          for (int k=0;k<HN;k++){
            float hk=s_h[k];
            lg0=fmaf(hk, s_wcurrT[k*HN+lane],    lg0);
            lg1=fmaf(hk, s_wcurrT[k*HN+lane+32], lg1);
          }
          float v = tanh_fast(s_prevfc[warp*HN+lane]   +lg0)*s_wout[lane]
                  + tanh_fast(s_prevfc[warp*HN+lane+32]+lg1)*s_wout[lane+32];
          #pragma unroll
          for (int off=16;off>0;off>>=1) v += __shfl_xor_sync(0xffffffffu, v, off);
          if (lane==0) s_dot[warp]=v;
        }
        __syncthreads();
        if (warp==0){
          float lgt = (lane<node) ? 1.1f*tanh_fast(s_dot[lane]) : -1e30f;
          sample(node, lgt);
        }
        __syncthreads();
        if (tid<HN) s_x[tid]=s_prevh[s_a*HN+tid];
        step++;
      }
      // ---- 2 op draws ----
      for (int t=0;t<2;t++){
        lstm();
        if (warp<5){
          float v = s_h[lane]*s_wops[warp*HN+lane] + s_h[lane+32]*s_wops[warp*HN+lane+32];
          #pragma unroll
          for (int off=16;off>0;off>>=1) v += __shfl_xor_sync(0xffffffffu, v, off);
          if (lane==0) s_dot[warp]=v;
        }
        __syncthreads();
        if (warp==0){
          float lgt = (lane<5) ? fmaf(0.44f, tanh_fast(s_dot[lane]+s_bops[lane]), s_abias[lane])
                               : -1e30f;
          sample(5, lgt);
        }
        __syncthreads();
        if (tid<HN) s_x[tid]=s_eops[s_a*HN+tid];
        step++;
      }
      // ---- node-closing LSTM step ----
      lstm();
      if (tid<HN){
        s_prevh[node*HN+tid]=s_h[tid];
        float b0=0.f,b1=0.f,b2=0.f,b3=0.f;
        #pragma unroll 16
        for (int k=0;k<HN;k+=4){
          b0=fmaf(s_h[k  ], s_wprevT[(k  )*HN+tid], b0);
          b1=fmaf(s_h[k+1], s_wprevT[(k+1)*HN+tid], b1);
          b2=fmaf(s_h[k+2], s_wprevT[(k+2)*HN+tid], b2);
          b3=fmaf(s_h[k+3], s_wprevT[(k+3)*HN+tid], b3);
        }
        s_prevfc[node*HN+tid]=(b0+b1)+(b2+b3);
        s_x[tid]=s_ef[tid];
      }
      // next lstm() entry sync covers these writes
    }
  }
}

extern "C" void kernel_launch(void* const* d_in, const int* in_sizes, int n_in,
                              void* d_out, int out_size)
{
  controller_kernel<<<1, NTHREADS>>>(
      (const float*)d_in[0],  // embed_first_w (1,64)
      (const float*)d_in[1],  // embed_ops_w   (5,64)
      (const float*)d_in[2],  // w_ih          (256,64)
      (const float*)d_in[3],  // w_hh          (256,64)
      (const float*)d_in[4],  // w_index_prev  (64,64)
      (const float*)d_in[5],  // w_index_curr  (64,64)
      (const float*)d_in[6],  // w_index_out   (1,64)
      (const float*)d_in[7],  // w_ops         (5,64)
      (const float*)d_in[8],  // b_ops         (5,)
      (const float*)d_in[9],  // additional_bias (5,)
      (float*)d_out, out_size);
}

// round 4
// speedup vs baseline: 1.3994x; 1.3994x over previous
#include <cuda_runtime.h>
#include <stdint.h>
#include <math.h>

#define HN 64
#define GN 256
#define NTHREADS 256

__device__ __forceinline__ uint32_t rotl32(uint32_t x, uint32_t r){ return (x<<r)|(x>>(32u-r)); }

// Threefry-2x32, 20 rounds, JAX key schedule.
__device__ __forceinline__ void tf2x32(uint32_t k0, uint32_t k1, uint32_t c0, uint32_t c1,
                                       uint32_t &o0, uint32_t &o1){
  uint32_t ks2 = k0 ^ k1 ^ 0x1BD11BDAu;
  uint32_t x0 = c0 + k0;
  uint32_t x1 = c1 + k1;
  x0+=x1; x1=rotl32(x1,13); x1^=x0;
  x0+=x1; x1=rotl32(x1,15); x1^=x0;
  x0+=x1; x1=rotl32(x1,26); x1^=x0;
  x0+=x1; x1=rotl32(x1, 6); x1^=x0;
  x0+=k1;  x1+=ks2+1u;
  x0+=x1; x1=rotl32(x1,17); x1^=x0;
  x0+=x1; x1=rotl32(x1,29); x1^=x0;
  x0+=x1; x1=rotl32(x1,16); x1^=x0;
  x0+=x1; x1=rotl32(x1,24); x1^=x0;
  x0+=ks2; x1+=k0+2u;
  x0+=x1; x1=rotl32(x1,13); x1^=x0;
  x0+=x1; x1=rotl32(x1,15); x1^=x0;
  x0+=x1; x1=rotl32(x1,26); x1^=x0;
  x0+=x1; x1=rotl32(x1, 6); x1^=x0;
  x0+=k0;  x1+=k1+3u;
  x0+=x1; x1=rotl32(x1,17); x1^=x0;
  x0+=x1; x1=rotl32(x1,29); x1^=x0;
  x0+=x1; x1=rotl32(x1,16); x1^=x0;
  x0+=x1; x1=rotl32(x1,24); x1^=x0;
  x0+=k1;  x1+=ks2+4u;
  x0+=x1; x1=rotl32(x1,13); x1^=x0;
  x0+=x1; x1=rotl32(x1,15); x1^=x0;
  x0+=x1; x1=rotl32(x1,26); x1^=x0;
  x0+=x1; x1=rotl32(x1, 6); x1^=x0;
  x0+=ks2; x1+=k0+5u;
  o0=x0; o1=x1;
}

// JAX partitionable uniform -> gumbel (accurate logs: computed once, off hot path)
__device__ __forceinline__ float bits2gumbel(uint32_t b){
  float u = __uint_as_float((b>>9)|0x3f800000u) - 1.0f;
  const float tiny = 1.17549435e-38f;
  u = fmaxf(tiny, u + tiny);
  return -logf(-logf(u));
}

__device__ __forceinline__ float sig_fast(float x){
  return __fdividef(1.0f, 1.0f + __expf(-x));
}
__device__ __forceinline__ float tanh_fast(float x){
  return 1.0f - __fdividef(2.0f, 1.0f + __expf(2.0f*x));
}

// warp-collective sample over n<=6 categories; lane<n holds lgt, else -1e30.
// lane0 writes outputs + *sa. Called by warp 0 only.
__device__ __forceinline__ void sample_warp(int lane, int n, float lgt,
                                            const float* gum_row,
                                            float* out, int step, int out_size,
                                            int* sa){
  float gum = (lane<n) ? (lgt + gum_row[lane]) : -1e30f;
  int idx = lane;
  #pragma unroll
  for (int off=4;off;off>>=1){
    float g2=__shfl_xor_sync(0xffffffffu,gum,off);
    int   i2=__shfl_xor_sync(0xffffffffu,idx,off);
    if (g2>gum || (g2==gum && i2<idx)){ gum=g2; idx=i2; }
  }
  float mx = lgt;
  #pragma unroll
  for (int off=4;off;off>>=1) mx = fmaxf(mx, __shfl_xor_sync(0xffffffffu,mx,off));
  float e = (lane<n) ? __expf(lgt-mx) : 0.f;
  float se = e;
  #pragma unroll
  for (int off=4;off;off>>=1) se += __shfl_xor_sync(0xffffffffu,se,off);
  float lse = __logf(se);
  float lp = lgt - mx - lse;
  float ec = (lane<n) ? -__expf(lp)*lp : 0.f;
  #pragma unroll
  for (int off=4;off;off>>=1) ec += __shfl_xor_sync(0xffffffffu,ec,off);
  float lpa = __shfl_sync(0xffffffffu, lp, idx);
  if (lane==0){
    if (step    < out_size) out[step]    = (float)idx;
    if (40+step < out_size) out[40+step] = ec;
    if (80+step < out_size) out[80+step] = lpa;
    *sa = idx;
  }
}

__global__ void __launch_bounds__(NTHREADS, 1)
controller_kernel(const float* __restrict__ ef, const float* __restrict__ eo,
                  const float* __restrict__ wih_g, const float* __restrict__ whh_g,
                  const float* __restrict__ wprev_g, const float* __restrict__ wcurr_g,
                  const float* __restrict__ wout_g, const float* __restrict__ wops_g,
                  const float* __restrict__ bops_g, const float* __restrict__ abias_g,
                  float* __restrict__ out, int out_size)
{
  __shared__ float s_wprevT[HN*HN];   // transposed: [k*64 + j]
  __shared__ float s_wcurrT[HN*HN];
  __shared__ float s_wops[5*HN];
  __shared__ float s_eops[5*HN];
  __shared__ float s_ef[HN];
  __shared__ float s_wout[HN];
  __shared__ float s_bops[8];
  __shared__ float s_abias[8];
  __shared__ float s_x[HN];
  __shared__ float s_h[HN];
  __shared__ float s_c[HN];
  __shared__ float s_g[GN];
  __shared__ float s_lg[HN];
  __shared__ float s_prevh[7*HN];
  __shared__ float s_prevfc[7*HN];
  __shared__ float s_gum[40*6];
  __shared__ float s_dot[8];
  __shared__ int   s_a;

  const int tid  = threadIdx.x;
  const int lane = tid & 31;
  const int warp = tid >> 5;

  // ---- cooperative loads ----
  for (int i=tid;i<HN;i+=NTHREADS){ s_ef[i]=ef[i]; s_wout[i]=wout_g[i]; }
  for (int i=tid;i<5*HN;i+=NTHREADS){ s_eops[i]=eo[i]; s_wops[i]=wops_g[i]; }
  if (tid<5){ s_bops[tid]=bops_g[tid]; s_abias[tid]=abias_g[tid]; }
  for (int i=tid;i<HN*HN;i+=NTHREADS){
    int j=i>>6, k=i&63;
    s_wprevT[k*HN+j]=wprev_g[i];
    s_wcurrT[k*HN+j]=wcurr_g[i];
  }
  float wih[HN], whh[HN];
  #pragma unroll
  for (int k=0;k<HN;k++){ wih[k]=wih_g[tid*HN+k]; whh[k]=whh_g[tid*HN+k]; }

  // ---- Gumbel table (input-independent; partitionable threefry) ----
  if (tid < 40){
    int r = tid % 20;
    int within = r & 3;
    int nd = 2 + (r>>2);
    int n  = (within<2) ? nd : 5;
    uint32_t k0,k1;
    tf2x32(0u, 42u, 0u, (uint32_t)(tid+1), k0, k1);   // fold_in(key(42), step)
    for (int i=0;i<n;i++){
      uint32_t o0,o1; tf2x32(k0,k1, 0u, (uint32_t)i, o0,o1);
      s_gum[tid*6+i] = bits2gumbel(o0 ^ o1);
    }
  }
  __syncthreads();

  if (tid<HN){ s_h[tid]=0.f; s_c[tid]=0.f; s_x[tid]=s_ef[tid]; }

  int step = 0;

  auto lstm = [&](){
    __syncthreads();                       // covers prior x/h writes
    float acc = 0.f;
    #pragma unroll
    for (int k=0;k<HN;k++) acc = fmaf(wih[k], s_x[k], acc);
    #pragma unroll
    for (int k=0;k<HN;k++) acc = fmaf(whh[k], s_h[k], acc);
    s_g[tid]=acc;
    __syncthreads();
    if (tid<HN){
      float ig=s_g[tid], fg=s_g[HN+tid], gg=s_g[2*HN+tid], og=s_g[3*HN+tid];
      float c = sig_fast(fg)*s_c[tid] + sig_fast(ig)*tanh_fast(gg);
      s_c[tid]=c;
      s_h[tid]=sig_fast(og)*tanh_fast(c);
    }
    __syncthreads();
  };

  for (int cell=0; cell<2; cell++){
    // two warm-up LSTM steps: prev_h <- 0, prev_fc <- h @ w_index_prev.T
    for (int t=0;t<2;t++){
      lstm();
      if (tid<HN){
        float acc=0.f;
        #pragma unroll
        for (int k=0;k<HN;k++) acc = fmaf(s_h[k], s_wprevT[k*HN+tid], acc);
        s_prevfc[t*HN+tid]=acc;
        s_prevh[t*HN+tid]=0.f;
      }
      __syncthreads();
    }
    for (int node=2; node<7; node++){
      // ---- 2 index draws ----
      for (int t=0;t<2;t++){
        lstm();
        if (tid<HN){
          float acc=0.f;
          #pragma unroll
          for (int k=0;k<HN;k++) acc = fmaf(s_h[k], s_wcurrT[k*HN+tid], acc);
          s_lg[tid]=acc;
        }
        __syncthreads();
        if (warp < node){   // q_i = tanh(prev_fc[i]+lg) . w_out
          float v = tanh_fast(s_prevfc[warp*HN+lane]    + s_lg[lane])    * s_wout[lane]
                  + tanh_fast(s_prevfc[warp*HN+lane+32] + s_lg[lane+32]) * s_wout[lane+32];
          #pragma unroll
          for (int off=16;off>0;off>>=1) v += __shfl_xor_sync(0xffffffffu, v, off);
          if (lane==0) s_dot[warp]=v;
        }
        __syncthreads();
        if (warp==0){
          float lgt = (lane<node) ? 1.1f*tanh_fast(s_dot[lane]) : -1e30f;
          sample_warp(lane, node, lgt, &s_gum[step*6], out, step, out_size, &s_a);
        }
        __syncthreads();
        if (tid<HN) s_x[tid]=s_prevh[s_a*HN+tid];
        step++;
      }
      // ---- 2 op draws ----
      for (int t=0;t<2;t++){
        lstm();
        if (warp<5){
          float v = s_h[lane]*s_wops[warp*HN+lane] + s_h[lane+32]*s_wops[warp*HN+lane+32];
          #pragma unroll
          for (int off=16;off>0;off>>=1) v += __shfl_xor_sync(0xffffffffu, v, off);
          if (lane==0) s_dot[warp]=v;
        }
        __syncthreads();
        if (warp==0){
          float lgt = (lane<5) ? fmaf(0.44f, tanh_fast(s_dot[lane]+s_bops[lane]), s_abias[lane])
                               : -1e30f;
          sample_warp(lane, 5, lgt, &s_gum[step*6], out, step, out_size, &s_a);
        }
        __syncthreads();
        if (tid<HN) s_x[tid]=s_eops[s_a*HN+tid];
        step++;
      }
      // ---- node-closing LSTM step ----
      lstm();
      if (tid<HN){
        s_prevh[node*HN+tid]=s_h[tid];
        float acc=0.f;
        #pragma unroll
        for (int k=0;k<HN;k++) acc = fmaf(s_h[k], s_wprevT[k*HN+tid], acc);
        s_prevfc[node*HN+tid]=acc;
        s_x[tid]=s_ef[tid];
      }
      // next lstm() entry sync covers these writes
    }
  }
}

extern "C" void kernel_launch(void* const* d_in, const int* in_sizes, int n_in,
                              void* d_out, int out_size)
{
  controller_kernel<<<1, NTHREADS>>>(
      (const float*)d_in[0],  // embed_first_w (1,64)
      (const float*)d_in[1],  // embed_ops_w   (5,64)
      (const float*)d_in[2],  // w_ih          (256,64)
      (const float*)d_in[3],  // w_hh          (256,64)
      (const float*)d_in[4],  // w_index_prev  (64,64)
      (const float*)d_in[5],  // w_index_curr  (64,64)
      (const float*)d_in[6],  // w_index_out   (1,64)
      (const float*)d_in[7],  // w_ops         (5,64)
      (const float*)d_in[8],  // b_ops         (5,)
      (const float*)d_in[9],  // additional_bias (5,)
      (float*)d_out, out_size);
}